// round 17
// baseline (speedup 1.0000x reference)
#include <cuda_runtime.h>
#include <cuda_fp16.h>
#include <math.h>
#include <stdint.h>

#define KK 128
#define ADIM 64
#define LDUR 6
#define TT 60
#define BSZ 1024
#define TH2 1024
#define NEGINF -1e38f

// ---- GEMM tiling ----
#define BM 128
#define BN 128
#define ROWB 80
#define MATB (BM * ROWB)
// fp16 (mm1): 3 tiles/stage (Ah, Al, Bh), BKT16=32 halves
#define STGB16 (3 * MATB)
#define SMEM16 (4 * STGB16)      // 122880
// int8 (mm2): 4 tiles/stage (Ah, Al, Bh, Bl), BKT8=64 int8 = 64B + 16 pad
#define STGB8 (4 * MATB)
#define SMEM8 (4 * STGB8)        // 163840

// ---------------- scratch ----------------
__device__ __align__(16) __half g_uh[(size_t)BSZ * TH2];
__device__ __align__(16) __half g_ul[(size_t)BSZ * TH2];
__device__ __align__(16) __half g_w1h[(size_t)8192 * 1024];
__device__ __align__(16) int8_t g_w2bh[(size_t)16384 * 8192];
__device__ __align__(16) int8_t g_w2bl[(size_t)16384 * 8192];
__device__ __align__(16) float  g_h[(size_t)BSZ * 8192];
__device__ __align__(16) int8_t g_ah[(size_t)BSZ * 8192];
__device__ __align__(16) int8_t g_al[(size_t)BSZ * 8192];
__device__ float g_sa[BSZ];
__device__ float g_sb[16384];
__device__ float g_cond[(size_t)BSZ * (KK * ADIM * 2)];
__device__ float g_pi[BSZ * KK];
__device__ float g_tsc[KK * KK];
__device__ float g_P[(size_t)BSZ * KK * KK];

__device__ __forceinline__ uint32_t smem_u32(const void* p) {
    uint32_t a;
    asm("{ .reg .u64 t; cvta.to.shared.u64 t, %1; cvt.u32.u64 %0, t; }" : "=r"(a) : "l"(p));
    return a;
}
#define CPASYNC16(sa, ga) \
    asm volatile("cp.async.cg.shared.global [%0], [%1], 16;" :: "r"(sa), "l"(ga) : "memory")
#define CPCOMMIT() asm volatile("cp.async.commit_group;" ::: "memory")
#define CPWAIT2()  asm volatile("cp.async.wait_group 2;" ::: "memory")

__device__ __forceinline__ void ldsm4(uint32_t* r, uint32_t a) {
    asm volatile("ldmatrix.sync.aligned.m8n8.x4.shared.b16 {%0,%1,%2,%3}, [%4];"
        : "=r"(r[0]), "=r"(r[1]), "=r"(r[2]), "=r"(r[3]) : "r"(a));
}
__device__ __forceinline__ void mma_f16(float* d, const uint32_t* a, const uint32_t* b) {
    asm volatile("mma.sync.aligned.m16n8k16.row.col.f32.f16.f16.f32 "
        "{%0,%1,%2,%3}, {%4,%5,%6,%7}, {%8,%9}, {%0,%1,%2,%3};"
        : "+f"(d[0]), "+f"(d[1]), "+f"(d[2]), "+f"(d[3])
        : "r"(a[0]), "r"(a[1]), "r"(a[2]), "r"(a[3]), "r"(b[0]), "r"(b[1]));
}
__device__ __forceinline__ void mma_s8(int* d, const uint32_t* a, const uint32_t* b) {
    asm volatile("mma.sync.aligned.m16n8k32.row.col.s32.s8.s8.s32 "
        "{%0,%1,%2,%3}, {%4,%5,%6,%7}, {%8,%9}, {%0,%1,%2,%3};"
        : "+r"(d[0]), "+r"(d[1]), "+r"(d[2]), "+r"(d[3])
        : "r"(a[0]), "r"(a[1]), "r"(a[2]), "r"(a[3]), "r"(b[0]), "r"(b[1]));
}

// ---------------- prep kernels ----------------
__global__ __launch_bounds__(256) void split_kernel(
    const float* __restrict__ in, __half* __restrict__ hi,
    __half* __restrict__ lo, size_t n)
{
    size_t i = (size_t)blockIdx.x * 256 + threadIdx.x;
    size_t st = (size_t)gridDim.x * 256;
    for (; i < n; i += st) {
        float v = in[i];
        __half h = __float2half_rn(v);
        hi[i] = h;
        lo[i] = __float2half_rn(v - __half2float(h));
    }
}

__global__ __launch_bounds__(256) void transpose_half_kernel(
    const float* __restrict__ in, __half* __restrict__ hi, int R, int C)
{
    __shared__ float t[64][65];
    int tx = threadIdx.x & 63, ty = threadIdx.x >> 6;
    int c0 = blockIdx.x * 64, r0 = blockIdx.y * 64;
    for (int r = ty; r < 64; r += 4) t[r][tx] = in[(size_t)(r0 + r) * C + c0 + tx];
    __syncthreads();
    for (int r = ty; r < 64; r += 4)
        hi[(size_t)(c0 + r) * R + r0 + tx] = __float2half_rn(t[tx][r]);
}

// column abs-max of W2 [8192][16384] -> sb[n] = max/127
__global__ __launch_bounds__(256) void colmax_kernel(
    const float* __restrict__ W, float* __restrict__ sb)
{
    int n = blockIdx.x * 256 + threadIdx.x;
    float mx = 0.f;
#pragma unroll 4
    for (int k = 0; k < 8192; k++) mx = fmaxf(mx, fabsf(W[(size_t)k * 16384 + n]));
    sb[n] = fmaxf(mx, 1e-20f) * (1.f / 127.f);
}

// W2 [8192][16384] fp32 -> Bh,Bl int8 [16384][8192] (transposed, 2-level quant)
__global__ __launch_bounds__(256) void tquant_kernel(
    const float* __restrict__ in, const float* __restrict__ sb,
    int8_t* __restrict__ bh, int8_t* __restrict__ bl)
{
    __shared__ float t[64][65];
    int tx = threadIdx.x & 63, ty = threadIdx.x >> 6;
    int c0 = blockIdx.x * 64, r0 = blockIdx.y * 64;   // c0: n, r0: k
    for (int r = ty; r < 64; r += 4) t[r][tx] = in[(size_t)(r0 + r) * 16384 + c0 + tx];
    __syncthreads();
    for (int r = ty; r < 64; r += 4) {
        int n = c0 + r;
        float s = sb[n];
        float v = t[tx][r];
        float qh = rintf(v / s);
        qh = fminf(fmaxf(qh, -127.f), 127.f);
        float rem = v - s * qh;
        float ql = rintf(rem * 128.f / s);
        ql = fminf(fmaxf(ql, -127.f), 127.f);
        size_t o = (size_t)n * 8192 + r0 + tx;
        bh[o] = (int8_t)qh;
        bl[o] = (int8_t)ql;
    }
}

// row abs-max of h [1024][8192] -> sa[m]
__global__ __launch_bounds__(256) void rowmax_kernel(
    const float* __restrict__ h, float* __restrict__ sa)
{
    __shared__ float red[256];
    int m = blockIdx.x, tid = threadIdx.x;
    float mx = 0.f;
    for (int k = tid; k < 8192; k += 256) mx = fmaxf(mx, fabsf(h[(size_t)m * 8192 + k]));
    red[tid] = mx; __syncthreads();
    for (int s = 128; s > 0; s >>= 1) { if (tid < s) red[tid] = fmaxf(red[tid], red[tid + s]); __syncthreads(); }
    if (tid == 0) sa[m] = fmaxf(red[0], 1e-20f) * (1.f / 127.f);
}

__global__ __launch_bounds__(256) void aquant_kernel(
    const float* __restrict__ h, const float* __restrict__ sa,
    int8_t* __restrict__ ah, int8_t* __restrict__ al)
{
    size_t i = (size_t)blockIdx.x * 256 + threadIdx.x;
    size_t st = (size_t)gridDim.x * 256;
    for (; i < (size_t)BSZ * 8192; i += st) {
        float s = sa[i >> 13];
        float v = h[i];
        float qh = rintf(v / s);
        qh = fminf(fmaxf(qh, -127.f), 127.f);
        float rem = v - s * qh;
        float ql = rintf(rem * 128.f / s);
        ql = fminf(fmaxf(ql, -127.f), 127.f);
        ah[i] = (int8_t)qh;
        al[i] = (int8_t)ql;
    }
}

// ---------------- mm1: fp16 2-pass, out = relu(D + bias) fp32 ----------------
__global__ __launch_bounds__(256, 1) void mm_f16_kernel(
    const __half* __restrict__ Agh, const __half* __restrict__ Agl,
    const __half* __restrict__ Bgh, const float* __restrict__ bias,
    float* __restrict__ out, int Nout, int Kd)
{
    extern __shared__ __align__(16) char smem[];
    const uint32_t sb0 = smem_u32(smem);
    const int tid = threadIdx.x, lane = tid & 31, wid = tid >> 5;
    const int wm = wid >> 1, wn = wid & 1;
    const int m0 = blockIdx.x * BM, n0 = blockIdx.y * BN;
    const int NC = Kd / 32;

    const __half* pAh = Agh + (size_t)m0 * Kd;
    const __half* pAl = Agl + (size_t)m0 * Kd;
    const __half* pBh = Bgh + (size_t)n0 * Kd;
    const int li0 = tid * 2;

    auto load_stage = [&](int c) {
        if (c < NC) {
            uint32_t sb = sb0 + (c & 3) * STGB16;
            int k0 = c * 32;
#pragma unroll
            for (int ii = 0; ii < 2; ii++) {
                int i = li0 + ii;
                int row = i >> 2, ch = i & 3;
                size_t go = (size_t)row * Kd + k0 + ch * 8;
                uint32_t so = (uint32_t)(row * ROWB + ch * 16);
                CPASYNC16(sb + so,            pAh + go);
                CPASYNC16(sb + MATB + so,     pAl + go);
                CPASYNC16(sb + 2 * MATB + so, pBh + go);
            }
        }
        CPCOMMIT();
    };

    float acc[2][8][4];
#pragma unroll
    for (int mt = 0; mt < 2; mt++)
#pragma unroll
        for (int nt = 0; nt < 8; nt++)
#pragma unroll
            for (int r = 0; r < 4; r++) acc[mt][nt][r] = 0.f;

    const uint32_t aoff = (uint32_t)((wm * 32 + (lane & 15)) * ROWB + (lane >> 4) * 16);
    const uint32_t boff = (uint32_t)((wn * 64 + (lane & 7) + ((lane >> 4) & 1) * 8) * ROWB
                                     + ((lane >> 3) & 1) * 16);

    load_stage(0); load_stage(1); load_stage(2);

    for (int c = 0; c < NC; c++) {
        CPWAIT2();
        __syncthreads();
        load_stage(c + 3);
        uint32_t sb = sb0 + (c & 3) * STGB16;
#pragma unroll
        for (int kk = 0; kk < 2; kk++) {
            uint32_t ah[2][4], al[2][4], bh[8][2];
#pragma unroll
            for (int mt = 0; mt < 2; mt++) {
                ldsm4(ah[mt], sb + aoff + mt * (16 * ROWB) + kk * 32);
                ldsm4(al[mt], sb + MATB + aoff + mt * (16 * ROWB) + kk * 32);
            }
#pragma unroll
            for (int np = 0; np < 4; np++) {
                uint32_t r[4];
                ldsm4(r, sb + 2 * MATB + boff + np * (16 * ROWB) + kk * 32);
                bh[2 * np][0] = r[0]; bh[2 * np][1] = r[1];
                bh[2 * np + 1][0] = r[2]; bh[2 * np + 1][1] = r[3];
            }
#pragma unroll
            for (int mt = 0; mt < 2; mt++)
#pragma unroll
                for (int nt = 0; nt < 8; nt++) {
                    mma_f16(acc[mt][nt], ah[mt], bh[nt]);
                    mma_f16(acc[mt][nt], al[mt], bh[nt]);
                }
        }
        __syncthreads();
    }

#pragma unroll
    for (int mt = 0; mt < 2; mt++) {
        int mrow = m0 + wm * 32 + mt * 16 + (lane >> 2);
#pragma unroll
        for (int nt = 0; nt < 8; nt++) {
            int n = n0 + wn * 64 + nt * 8 + (lane & 3) * 2;
            float b0 = bias[n], b1 = bias[n + 1];
            float v0 = fmaxf(acc[mt][nt][0] + b0, 0.f), v1 = fmaxf(acc[mt][nt][1] + b1, 0.f);
            float v2 = fmaxf(acc[mt][nt][2] + b0, 0.f), v3 = fmaxf(acc[mt][nt][3] + b1, 0.f);
            *(float2*)(out + (size_t)mrow * Nout + n)       = make_float2(v0, v1);
            *(float2*)(out + (size_t)(mrow + 8) * Nout + n) = make_float2(v2, v3);
        }
    }
}

// ---------------- mm2: int8 3-pass (AhBh; AhBl+AlBh) ----------------
__global__ __launch_bounds__(256, 1) void mm_s8_kernel(
    const int8_t* __restrict__ Agh, const int8_t* __restrict__ Agl,
    const int8_t* __restrict__ Bgh, const int8_t* __restrict__ Bgl,
    const float* __restrict__ sa, const float* __restrict__ sb,
    const float* __restrict__ bias, float* __restrict__ out,
    int Nout, int Kd)
{
    extern __shared__ __align__(16) char smem[];
    const uint32_t sb0 = smem_u32(smem);
    const int tid = threadIdx.x, lane = tid & 31, wid = tid >> 5;
    const int wm = wid >> 1, wn = wid & 1;
    const int m0 = blockIdx.x * BM, n0 = blockIdx.y * BN;
    const int NC = Kd / 64;

    const int8_t* pAh = Agh + (size_t)m0 * Kd;
    const int8_t* pAl = Agl + (size_t)m0 * Kd;
    const int8_t* pBh = Bgh + (size_t)n0 * Kd;
    const int8_t* pBl = Bgl + (size_t)n0 * Kd;
    const int li0 = tid * 2;

    auto load_stage = [&](int c) {
        if (c < NC) {
            uint32_t sb_ = sb0 + (c & 3) * STGB8;
            int k0 = c * 64;
#pragma unroll
            for (int ii = 0; ii < 2; ii++) {
                int i = li0 + ii;
                int row = i >> 2, ch = i & 3;
                size_t go = (size_t)row * Kd + k0 + ch * 16;
                uint32_t so = (uint32_t)(row * ROWB + ch * 16);
                CPASYNC16(sb_ + so,            pAh + go);
                CPASYNC16(sb_ + MATB + so,     pAl + go);
                CPASYNC16(sb_ + 2 * MATB + so, pBh + go);
                CPASYNC16(sb_ + 3 * MATB + so, pBl + go);
            }
        }
        CPCOMMIT();
    };

    int acc1[2][8][4], acc2[2][8][4];
#pragma unroll
    for (int mt = 0; mt < 2; mt++)
#pragma unroll
        for (int nt = 0; nt < 8; nt++)
#pragma unroll
            for (int r = 0; r < 4; r++) { acc1[mt][nt][r] = 0; acc2[mt][nt][r] = 0; }

    const uint32_t aoff = (uint32_t)((wm * 32 + (lane & 15)) * ROWB + (lane >> 4) * 16);
    const uint32_t boff = (uint32_t)((wn * 64 + (lane & 7) + ((lane >> 4) & 1) * 8) * ROWB
                                     + ((lane >> 3) & 1) * 16);

    load_stage(0); load_stage(1); load_stage(2);

    for (int c = 0; c < NC; c++) {
        CPWAIT2();
        __syncthreads();
        load_stage(c + 3);
        uint32_t sb_ = sb0 + (c & 3) * STGB8;
#pragma unroll
        for (int kk = 0; kk < 2; kk++) {
            uint32_t ah[2][4], al[2][4], bh[8][2], bl[8][2];
#pragma unroll
            for (int mt = 0; mt < 2; mt++) {
                ldsm4(ah[mt], sb_ + aoff + mt * (16 * ROWB) + kk * 32);
                ldsm4(al[mt], sb_ + MATB + aoff + mt * (16 * ROWB) + kk * 32);
            }
#pragma unroll
            for (int np = 0; np < 4; np++) {
                uint32_t r[4];
                ldsm4(r, sb_ + 2 * MATB + boff + np * (16 * ROWB) + kk * 32);
                bh[2 * np][0] = r[0]; bh[2 * np][1] = r[1];
                bh[2 * np + 1][0] = r[2]; bh[2 * np + 1][1] = r[3];
                ldsm4(r, sb_ + 3 * MATB + boff + np * (16 * ROWB) + kk * 32);
                bl[2 * np][0] = r[0]; bl[2 * np][1] = r[1];
                bl[2 * np + 1][0] = r[2]; bl[2 * np + 1][1] = r[3];
            }
#pragma unroll
            for (int mt = 0; mt < 2; mt++)
#pragma unroll
                for (int nt = 0; nt < 8; nt++) {
                    mma_s8(acc1[mt][nt], ah[mt], bh[nt]);
                    mma_s8(acc2[mt][nt], ah[mt], bl[nt]);
                    mma_s8(acc2[mt][nt], al[mt], bh[nt]);
                }
        }
        __syncthreads();
    }

#pragma unroll
    for (int mt = 0; mt < 2; mt++) {
        int mrow = m0 + wm * 32 + mt * 16 + (lane >> 2);
        float sa0 = sa[mrow], sa1 = sa[mrow + 8];
#pragma unroll
        for (int nt = 0; nt < 8; nt++) {
            int n = n0 + wn * 64 + nt * 8 + (lane & 3) * 2;
            float sb0f = sb[n], sb1f = sb[n + 1];
            float b0 = bias[n], b1 = bias[n + 1];
            const float inv128 = 1.f / 128.f;
            float v0 = sa0 * sb0f * ((float)acc1[mt][nt][0] + (float)acc2[mt][nt][0] * inv128) + b0;
            float v1 = sa0 * sb1f * ((float)acc1[mt][nt][1] + (float)acc2[mt][nt][1] * inv128) + b1;
            float v2 = sa1 * sb0f * ((float)acc1[mt][nt][2] + (float)acc2[mt][nt][2] * inv128) + b0;
            float v3 = sa1 * sb1f * ((float)acc1[mt][nt][3] + (float)acc2[mt][nt][3] * inv128) + b1;
            *(float2*)(out + (size_t)mrow * Nout + n)       = make_float2(v0, v1);
            *(float2*)(out + (size_t)(mrow + 8) * Nout + n) = make_float2(v2, v3);
        }
    }
}

// ---------------- pi: 4 rows/block, 256 blocks ----------------
__global__ __launch_bounds__(256) void pi_kernel(
    const float* __restrict__ uniq, const float* __restrict__ W,
    const float* __restrict__ b, float* __restrict__ pi)
{
    __shared__ float us[4][1024];
    __shared__ float part[2][4][128];
    int r0 = blockIdx.x * 4, tid = threadIdx.x;
    for (int idx = tid; idx < 4096; idx += 256)
        us[idx >> 10][idx & 1023] = uniq[(size_t)(r0 + (idx >> 10)) * TH2 + (idx & 1023)];
    __syncthreads();
    int k = tid & 127, hf = tid >> 7;
    float a0 = 0.f, a1 = 0.f, a2 = 0.f, a3 = 0.f;
    int i0 = hf * 512;
#pragma unroll 4
    for (int i = i0; i < i0 + 512; i++) {
        float w = W[i * KK + k];
        a0 += us[0][i] * w; a1 += us[1][i] * w;
        a2 += us[2][i] * w; a3 += us[3][i] * w;
    }
    part[hf][0][k] = a0; part[hf][1][k] = a1; part[hf][2][k] = a2; part[hf][3][k] = a3;
    __syncthreads();
    int wid = tid >> 5, lane = tid & 31;
    if (wid < 4) {
        float v[4]; float m = -INFINITY;
#pragma unroll
        for (int q = 0; q < 4; q++) {
            int kk = lane + q * 32;
            v[q] = part[0][wid][kk] + part[1][wid][kk] + b[kk];
            m = fmaxf(m, v[q]);
        }
#pragma unroll
        for (int off = 16; off; off >>= 1) m = fmaxf(m, __shfl_xor_sync(0xffffffffu, m, off));
        float s = 0.f;
#pragma unroll
        for (int q = 0; q < 4; q++) s += expf(v[q] - m);
#pragma unroll
        for (int off = 16; off; off >>= 1) s += __shfl_xor_sync(0xffffffffu, s, off);
        float lse = m + logf(s);
#pragma unroll
        for (int q = 0; q < 4; q++)
            pi[(size_t)(r0 + wid) * KK + lane + q * 32] = v[q] - lse;
    }
}

__global__ __launch_bounds__(128) void tsc_kernel(
    const float* __restrict__ Af, const float* __restrict__ At, float* __restrict__ tsc)
{
    int k = blockIdx.x, j = threadIdx.x;
    float acc = 0.f;
#pragma unroll
    for (int a = 0; a < ADIM; a++) acc += Af[k * ADIM + a] * At[a * KK + j];
    if (k == j) acc += NEGINF;
    tsc[k * KK + j] = acc;
}

// ---------------- trans -> P ----------------
__global__ __launch_bounds__(256) void trans_kernel(
    const float* __restrict__ cond, const float* __restrict__ tsc, float* __restrict__ P)
{
    extern __shared__ float sm[];
    float* fr = sm;
    float* to = sm + KK * ADIM;
    float* tr = sm;
    int b = blockIdx.x, tid = threadIdx.x;
    const float* cb = cond + (size_t)b * KK * 2 * ADIM;
    for (int idx = tid; idx < KK * 2 * ADIM; idx += 256) {
        int kk = idx >> 7, a = idx & 127;
        float v = cb[idx];
        if (a < ADIM) fr[kk * ADIM + a] = v;
        else          to[kk * ADIM + (a - ADIM)] = v;
    }
    __syncthreads();
    int tx = tid & 15, ty = tid >> 4;
    float acc[8][8];
#pragma unroll
    for (int i = 0; i < 8; i++)
#pragma unroll
        for (int j = 0; j < 8; j++) acc[i][j] = 0.f;
#pragma unroll 4
    for (int a = 0; a < ADIM; a++) {
        float ra[8], rb[8];
#pragma unroll
        for (int i = 0; i < 8; i++) ra[i] = fr[(ty * 8 + i) * ADIM + a];
#pragma unroll
        for (int j = 0; j < 8; j++) rb[j] = to[(tx * 8 + j) * ADIM + a];
#pragma unroll
        for (int i = 0; i < 8; i++)
#pragma unroll
            for (int j = 0; j < 8; j++) acc[i][j] += ra[i] * rb[j];
    }
    __syncthreads();
#pragma unroll
    for (int i = 0; i < 8; i++)
#pragma unroll
        for (int j = 0; j < 8; j++)
            tr[(ty * 8 + i) * KK + tx * 8 + j] = acc[i][j] + tsc[(ty * 8 + i) * KK + tx * 8 + j];
    __syncthreads();
    int wid = tid >> 5, lane = tid & 31;
    for (int row = wid; row < KK; row += 8) {
        float v[4]; float m = -INFINITY;
#pragma unroll
        for (int i = 0; i < 4; i++) { v[i] = tr[row * KK + lane + i * 32]; m = fmaxf(m, v[i]); }
#pragma unroll
        for (int off = 16; off; off >>= 1) m = fmaxf(m, __shfl_xor_sync(0xffffffffu, m, off));
        float e[4]; float s = 0.f;
#pragma unroll
        for (int i = 0; i < 4; i++) { e[i] = expf(v[i] - m); s += e[i]; }
#pragma unroll
        for (int off = 16; off; off >>= 1) s += __shfl_xor_sync(0xffffffffu, s, off);
        float inv = 1.0f / s;
#pragma unroll
        for (int i = 0; i < 4; i++)
            P[(size_t)b * KK * KK + row * KK + lane + i * 32] = e[i] * inv;
    }
}

// ---------------- scan ----------------
__global__ __launch_bounds__(128) void scan_kernel(
    const float* __restrict__ obs, const float* __restrict__ pi,
    const float* __restrict__ Pg, float* __restrict__ out)
{
    extern __shared__ float sm[];
    float* Psm  = sm;
    float* buf  = sm + KK * KK;
    float* pvec = buf + LDUR * KK;
    float* red  = pvec + KK;
    int b = blockIdx.x, j = threadIdx.x;
    const float len_lp = -1.7917594692280550f;
    {
        const float4* src = (const float4*)(Pg + (size_t)b * KK * KK);
        float4* dst = (float4*)Psm;
        for (int i = j; i < KK * KK / 4; i += 128) dst[i] = src[i];
    }
    buf[j] = pi[b * KK + j];
#pragma unroll
    for (int l = 1; l < LDUR; l++) buf[l * KK + j] = NEGINF;
    __syncthreads();
    int base = 0;
    for (int t = 0; t < TT; t++) {
        float vs[LDUR], vmax = -INFINITY;
#pragma unroll
        for (int l = 0; l < LDUR; l++) {
            int st = t - l;
            float v = NEGINF;
            if (st >= 0)
                v = buf[((base + l) % LDUR) * KK + j] + obs[(((size_t)l * TT + st) * BSZ + b) * KK + j] + len_lp;
            vs[l] = v; vmax = fmaxf(vmax, v);
        }
        float alpha;
        if (vmax < -1e30f) alpha = NEGINF;
        else {
            float s = 0.f;
#pragma unroll
            for (int l = 0; l < LDUR; l++) s += expf(vs[l] - vmax);
            alpha = vmax + logf(s);
        }
        red[j] = alpha; __syncthreads();
        for (int s2 = 64; s2; s2 >>= 1) { if (j < s2) red[j] = fmaxf(red[j], red[j + s2]); __syncthreads(); }
        float M = red[0];
        __syncthreads();
        pvec[j] = expf(alpha - M);
        __syncthreads();
        if (t == TT - 1) {
            red[j] = pvec[j]; __syncthreads();
            for (int s2 = 64; s2; s2 >>= 1) { if (j < s2) red[j] += red[j + s2]; __syncthreads(); }
            if (j == 0) out[b] = M + logf(red[0]);
            break;
        }
        float a0 = 0.f, a1 = 0.f, a2 = 0.f, a3 = 0.f;
#pragma unroll 8
        for (int kk = 0; kk < KK; kk += 4) {
            a0 += pvec[kk + 0] * Psm[(kk + 0) * KK + j];
            a1 += pvec[kk + 1] * Psm[(kk + 1) * KK + j];
            a2 += pvec[kk + 2] * Psm[(kk + 2) * KK + j];
            a3 += pvec[kk + 3] * Psm[(kk + 3) * KK + j];
        }
        float astar = M + logf((a0 + a1) + (a2 + a3));
        base = (base + LDUR - 1) % LDUR;
        buf[base * KK + j] = astar;
        __syncthreads();
    }
}

// ---------------- launch ----------------
extern "C" void kernel_launch(void* const* d_in, const int* in_sizes, int n_in,
                              void* d_out, int out_size)
{
    const float* uniqenc = (const float*)d_in[0];
    const float* obs_lps = (const float*)d_in[1];
    const float* W_init  = (const float*)d_in[2];
    const float* b_init  = (const float*)d_in[3];
    const float* A_from  = (const float*)d_in[4];
    const float* A_to    = (const float*)d_in[5];
    const float* W_c1    = (const float*)d_in[6];
    const float* b_c1    = (const float*)d_in[7];
    const float* W_c2    = (const float*)d_in[8];
    const float* b_c2    = (const float*)d_in[9];
    float* out = (float*)d_out;

    void *p_uh, *p_ul, *p_w1h, *p_w2bh, *p_w2bl, *p_h, *p_ah, *p_al, *p_sa, *p_sb;
    float *p_cond, *p_pi, *p_tsc, *p_P;
    cudaGetSymbolAddress(&p_uh, g_uh);     cudaGetSymbolAddress(&p_ul, g_ul);
    cudaGetSymbolAddress(&p_w1h, g_w1h);
    cudaGetSymbolAddress(&p_w2bh, g_w2bh); cudaGetSymbolAddress(&p_w2bl, g_w2bl);
    cudaGetSymbolAddress(&p_h, g_h);
    cudaGetSymbolAddress(&p_ah, g_ah);     cudaGetSymbolAddress(&p_al, g_al);
    cudaGetSymbolAddress(&p_sa, g_sa);     cudaGetSymbolAddress(&p_sb, g_sb);
    cudaGetSymbolAddress((void**)&p_cond, g_cond);
    cudaGetSymbolAddress((void**)&p_pi, g_pi);
    cudaGetSymbolAddress((void**)&p_tsc, g_tsc);
    cudaGetSymbolAddress((void**)&p_P, g_P);

    cudaFuncSetAttribute(mm_f16_kernel, cudaFuncAttributeMaxDynamicSharedMemorySize, SMEM16);
    cudaFuncSetAttribute(mm_s8_kernel, cudaFuncAttributeMaxDynamicSharedMemorySize, SMEM8);
    cudaFuncSetAttribute(trans_kernel, cudaFuncAttributeMaxDynamicSharedMemorySize,
                         (2 * KK * ADIM) * (int)sizeof(float));
    cudaFuncSetAttribute(scan_kernel, cudaFuncAttributeMaxDynamicSharedMemorySize,
                         (KK * KK + LDUR * KK + 2 * KK) * (int)sizeof(float));

    split_kernel<<<2048, 256>>>(uniqenc, (__half*)p_uh, (__half*)p_ul, (size_t)BSZ * TH2);
    {   dim3 g(8192 / 64, 1024 / 64);
        transpose_half_kernel<<<g, 256>>>(W_c1, (__half*)p_w1h, 1024, 8192); }
    colmax_kernel<<<64, 256>>>(W_c2, (float*)p_sb);
    {   dim3 g(16384 / 64, 8192 / 64);
        tquant_kernel<<<g, 256>>>(W_c2, (const float*)p_sb, (int8_t*)p_w2bh, (int8_t*)p_w2bl); }
    pi_kernel<<<256, 256>>>(uniqenc, W_init, b_init, p_pi);
    tsc_kernel<<<KK, 128>>>(A_from, A_to, p_tsc);

    // h = relu(uniq @ W1 + b1) fp32
    {   dim3 g(1024 / BM, 8192 / BN);
        mm_f16_kernel<<<g, 256, SMEM16>>>(
            (const __half*)p_uh, (const __half*)p_ul, (const __half*)p_w1h,
            b_c1, (float*)p_h, 8192, 1024); }
    rowmax_kernel<<<BSZ, 256>>>((const float*)p_h, (float*)p_sa);
    aquant_kernel<<<2048, 256>>>((const float*)p_h, (const float*)p_sa,
                                 (int8_t*)p_ah, (int8_t*)p_al);
    // cond = h @ W2 + b2 (int8 3-pass)
    {   dim3 g(1024 / BM, 16384 / BN);
        mm_s8_kernel<<<g, 256, SMEM8>>>(
            (const int8_t*)p_ah, (const int8_t*)p_al,
            (const int8_t*)p_w2bh, (const int8_t*)p_w2bl,
            (const float*)p_sa, (const float*)p_sb,
            b_c2, p_cond, 16384, 8192); }

    trans_kernel<<<BSZ, 256, (2 * KK * ADIM) * sizeof(float)>>>(p_cond, p_tsc, p_P);
    scan_kernel<<<BSZ, 128, (KK * KK + LDUR * KK + 2 * KK) * sizeof(float)>>>(obs_lps, p_pi, p_P, out);

    (void)in_sizes; (void)n_in; (void)out_size;
}